// round 17
// baseline (speedup 1.0000x reference)
#include <cuda_runtime.h>

typedef unsigned long long u64;
typedef unsigned u32;
#define DI __device__ __forceinline__

// ---------- packed f32x2 helpers (PTX-only on sm_103a) ----------
DI u64 pack2(float lo, float hi) {
    u64 r;
    asm("mov.b64 %0, {%1, %2};"
        : "=l"(r) : "r"(__float_as_uint(lo)), "r"(__float_as_uint(hi)));
    return r;
}
DI u64 dup2(float v) {
    u64 r;
    asm("mov.b64 %0, {%1, %1};" : "=l"(r) : "r"(__float_as_uint(v)));
    return r;
}
DI void unpack2(u64 v, u32& lo, u32& hi) {
    asm("mov.b64 {%0, %1}, %2;" : "=r"(lo), "=r"(hi) : "l"(v));
}
DI u64 fma2(u64 a, u64 b, u64 c) {
    u64 d;
    asm("fma.rn.f32x2 %0, %1, %2, %3;" : "=l"(d) : "l"(a), "l"(b), "l"(c));
    return d;
}
DI u32 prmt(u32 a, u32 b, u32 sel) {
    u32 d;
    asm("prmt.b32 %0, %1, %2, %3;" : "=r"(d) : "r"(a), "r"(b), "r"(sel));
    return d;
}
// sign bytes of 4 floats -> [sA,sB,sC,sD] (0xFF where negative)
DI u32 sgn4(u32 a, u32 b, u32 c, u32 d) {
    const u32 ab = prmt(a, b, 0xFBFB);
    const u32 cd = prmt(c, d, 0xFBFB);
    return prmt(ab, cd, 0x5410);
}
// signed dp4a: sign bytes (0xFF = -1) x negated weights -> positive index
DI u32 dp4as(u32 a, u32 b) {
    int d;
    asm("dp4a.s32.s32 %0, %1, %2, %3;" : "=r"(d) : "r"(a), "r"(b), "r"(0));
    return (u32)d;
}

__global__ void __launch_bounds__(128, 6) toy_force_kernel(
    const float4* __restrict__ pos,
    const float*  __restrict__ W1,   // [8,2]
    const float*  __restrict__ b1,   // [8]
    const float*  __restrict__ W2,   // [4,8]
    const float*  __restrict__ b2,   // [4]
    const float*  __restrict__ W3,   // [2,4]
    float4*       __restrict__ out,
    int npairs)
{
    __shared__ float u_s[16][8];  // u(m2)_i = sum_{j act} (-v3_j) W2[j][i]
    __shared__ u64 ftab[4096];    // force per (m1, m2): entry m1 + 256*m2

    const int tid = threadIdx.x;

    // ---- u table: one (m2, i) per thread ----
    {
        const int i = tid & 7, m = tid >> 3;
        float s = 0.f;
#pragma unroll
        for (int j = 0; j < 4; j++) {
            const float v3n = -(__ldg(&W3[j]) + __ldg(&W3[4 + j]));  // fold -grad
            if (!((m >> j) & 1)) s += v3n * __ldg(&W2[8 * j + i]);
        }
        u_s[m][i] = s;
    }
    __syncthreads();

    // ---- combined force table: 4096 entries (32 per thread) ----
    {
        float w1c[16];
#pragma unroll
        for (int t = 0; t < 16; t++) w1c[t] = __ldg(&W1[t]);
        for (int e = tid; e < 4096; e += blockDim.x) {
            const int m2 = e >> 8;
            float fx = 0.f, fy = 0.f;
#pragma unroll
            for (int i = 0; i < 8; i++) {
                const float msk = ((e >> i) & 1) ? 0.f : 1.f;  // bit = inactive
                const float ui = msk * u_s[m2][i];
                fx = fmaf(ui, w1c[2 * i], fx);
                fy = fmaf(ui, w1c[2 * i + 1], fy);
            }
            ftab[e] = pack2(fx, fy);
        }
    }
    __syncthreads();

    // ---- register-resident weights, neuron-pair packed (32 u64) ----
    u64 W1px[4], W1py[4], B1p[4], W2np[4][4], B2p[4];
#pragma unroll
    for (int k = 0; k < 4; k++) {
        W1px[k] = pack2(__ldg(&W1[4 * k]),     __ldg(&W1[4 * k + 2]));
        W1py[k] = pack2(__ldg(&W1[4 * k + 1]), __ldg(&W1[4 * k + 3]));
        B1p[k]  = pack2(__ldg(&b1[2 * k]),     __ldg(&b1[2 * k + 1]));
    }
#pragma unroll
    for (int j = 0; j < 4; j++) {
#pragma unroll
        for (int k = 0; k < 4; k++)
            W2np[j][k] = pack2(__ldg(&W2[8 * j + 2 * k]),
                               __ldg(&W2[8 * j + 2 * k + 1]));
        B2p[j] = pack2(__ldg(&b2[j]), 0.f);    // b2 folded into acc seed
    }

    const char* tb = (const char*)ftab;
    const u32 K1n = 0xC0E0F0F8u;  // byte weights -8,-16,-32,-64 (m1 * 8B)
    const u32 K2n = 0xF8FCFEFFu;  // byte weights -1,-2,-4,-8    (m2 value)

    // one 2-D position -> packed force (f32x2), single table lookup
    auto evalPos = [&](float x, float y) -> u64 {
        const u64 X = dup2(x), Y = dup2(y);
        u32 z[8];
        u64 Hp[4];
#pragma unroll
        for (int k = 0; k < 4; k++) {
            const u64 zp = fma2(W1px[k], X, fma2(W1py[k], Y, B1p[k]));
            unpack2(zp, z[2 * k], z[2 * k + 1]);
            Hp[k] = pack2(fmaxf(__uint_as_float(z[2 * k]), 0.f),
                          fmaxf(__uint_as_float(z[2 * k + 1]), 0.f));
        }
        u32 z2v[4];
#pragma unroll
        for (int j = 0; j < 4; j++) {
            u64 acc = fma2(W2np[j][0], Hp[0], B2p[j]);   // seed carries b2
            acc = fma2(W2np[j][1], Hp[1], acc);
            acc = fma2(W2np[j][2], Hp[2], acc);
            acc = fma2(W2np[j][3], Hp[3], acc);
            u32 lo, hi;
            unpack2(acc, lo, hi);
            z2v[j] = __float_as_uint(__uint_as_float(lo) + __uint_as_float(hi));
        }
        const u32 d1a = dp4as(sgn4(z[0], z[1], z[2], z[3]), K1n);    // m1lo*8
        const u32 d1b = dp4as(sgn4(z[4], z[5], z[6], z[7]), K1n);    // m1hi*8
        const u32 m2v = dp4as(sgn4(z2v[0], z2v[1], z2v[2], z2v[3]), K2n);
        const u32 off = d1a + (d1b << 4) + (m2v << 11);
        return *(const u64*)(tb + off);
    };

    auto evalStore = [&](int k, const float4 p) {
        const u64 F0 = evalPos(p.x, p.y);
        const u64 F1 = evalPos(p.z, p.w);
        *(ulonglong2*)&out[k] = make_ulonglong2(F0, F1);
    };

    const int stride = gridDim.x * blockDim.x;
    int k = blockIdx.x * blockDim.x + tid;
    if (k >= npairs) return;

    // counted main loop: 3 streams, no bounds checks, rotating prefetch
    const int cnt = (npairs - 1 - k) / stride + 1;
    const int nfull = cnt / 3;
    const int r = cnt - 3 * nfull;

    if (nfull > 0) {
        float4 pa = pos[k];
        float4 pb = pos[k + stride];
        float4 pc = pos[k + 2 * stride];
        for (int it = 1; it < nfull; it++) {
            const int kn = k + 3 * stride;
            const float4 na = pos[kn];
            const float4 nb = pos[kn + stride];
            const float4 nc = pos[kn + 2 * stride];
            evalStore(k, pa);
            evalStore(k + stride, pb);
            evalStore(k + 2 * stride, pc);
            pa = na; pb = nb; pc = nc;
            k = kn;
        }
        evalStore(k, pa);
        evalStore(k + stride, pb);
        evalStore(k + 2 * stride, pc);
        k += 3 * stride;
    }
    for (int m = 0; m < r; m++) {
        const int kt = k + m * stride;
        evalStore(kt, pos[kt]);
    }
}

extern "C" void kernel_launch(void* const* d_in, const int* in_sizes, int n_in,
                              void* d_out, int out_size) {
    const float* pos = (const float*)d_in[0];
    const float* W1  = (const float*)d_in[1];
    const float* b1  = (const float*)d_in[2];
    const float* W2  = (const float*)d_in[3];
    const float* b2  = (const float*)d_in[4];
    const float* W3  = (const float*)d_in[5];
    float* out = (float*)d_out;

    const int npairs = in_sizes[0] / 4;   // one float4 = 2 positions

    const int threads = 128;
    const int blocks  = 888;              // 148 SMs x 6 CTAs
    toy_force_kernel<<<blocks, threads>>>(
        (const float4*)pos, W1, b1, W2, b2, W3, (float4*)out, npairs);
}